// round 5
// baseline (speedup 1.0000x reference)
#include <cuda_runtime.h>
#include <cstdint>

// DurationCalculator: B=256, Y=4096, X=1024
//   weights_argmax[b,y] = duration[b,y] + (y < output_length[b] ? 0 : -10000)
//   durations[b,x]      = #{ y < output_length[b] : duration[b,y] == x }
// duration values are in [0, X): all valid elements in range, all masked
// elements drop below 0 (reference clips them into the discarded bucket).
// Output dtype float32. Layout: [B*Y weights_argmax][B*X durations].
//
// Single kernel: 512 CTAs = 2 per row, clustered in pairs. Each CTA
// histograms its half-row into private smem (halves the worst-case serialized
// ATOMS chain vs one-CTA-per-row), then the pair merges over DSMEM after a
// cluster barrier — no second kernel, no global scratch.

#define B_DIM 256
#define Y_DIM 4096
#define X_DIM 1024
#define MASK_PENALTY (-10000)

__global__ __cluster_dims__(2, 1, 1) __launch_bounds__(512, 4)
void duration_calc_kernel(const int* __restrict__ duration,
                          const int* __restrict__ output_length,
                          float* __restrict__ weights_out,
                          float* __restrict__ hist_out)
{
    __shared__ int hist[X_DIM];

    const int tid  = threadIdx.x;                 // 0..511
    const int row  = blockIdx.x >> 1;             // 0..255
    uint32_t rank;                                // 0 or 1 within cluster
    asm("mov.u32 %0, %%cluster_ctarank;" : "=r"(rank));

    hist[tid]       = 0;
    hist[tid + 512] = 0;
    __syncthreads();

    const int len = __ldg(&output_length[row]);

    // Half-row = 2048 ints = 512 int4; one int4 per thread.
    const int gid4 = row * (Y_DIM / 4) + (int)rank * 512 + tid;
    const int y0   = ((int)rank * 512 + tid) * 4;

    const int4 v = reinterpret_cast<const int4*>(duration)[gid4];

    const bool m0 = (y0 + 0) < len;
    const bool m1 = (y0 + 1) < len;
    const bool m2 = (y0 + 2) < len;
    const bool m3 = (y0 + 3) < len;

    float4 w;
    w.x = (float)(v.x + (m0 ? 0 : MASK_PENALTY));
    w.y = (float)(v.y + (m1 ? 0 : MASK_PENALTY));
    w.z = (float)(v.z + (m2 ? 0 : MASK_PENALTY));
    w.w = (float)(v.w + (m3 ? 0 : MASK_PENALTY));

    reinterpret_cast<float4*>(weights_out)[gid4] = w;

    if (m0) atomicAdd(&hist[v.x], 1);
    if (m1) atomicAdd(&hist[v.y], 1);
    if (m2) atomicAdd(&hist[v.z], 1);
    if (m3) atomicAdd(&hist[v.w], 1);

    // Cluster barrier: release our smem atomics, acquire peer's.
    asm volatile("barrier.cluster.arrive.aligned;" ::: "memory");
    asm volatile("barrier.cluster.wait.aligned;"   ::: "memory");

    // Merge: rank 0 emits bins [0,512), rank 1 emits bins [512,1024).
    // Each thread sums its local bin with the peer's same bin over DSMEM.
    const int bin = (int)rank * 512 + tid;

    uint32_t laddr;
    asm("{ .reg .u64 t; cvta.to.shared.u64 t, %1; cvt.u32.u64 %0, t; }"
        : "=r"(laddr) : "l"(&hist[bin]));

    uint32_t raddr;
    const uint32_t peer = rank ^ 1u;
    asm("mapa.shared::cluster.u32 %0, %1, %2;" : "=r"(raddr) : "r"(laddr), "r"(peer));

    int rv;
    asm volatile("ld.shared::cluster.s32 %0, [%1];" : "=r"(rv) : "r"(raddr));

    hist_out[(size_t)row * X_DIM + bin] = (float)(hist[bin] + rv);

    // No CTA may exit while its peer still reads our smem.
    asm volatile("barrier.cluster.arrive.aligned;" ::: "memory");
    asm volatile("barrier.cluster.wait.aligned;"   ::: "memory");
}

extern "C" void kernel_launch(void* const* d_in, const int* in_sizes, int n_in,
                              void* d_out, int out_size)
{
    const int* duration      = (const int*)d_in[0];   // (B, Y) int32
    const int* output_length = (const int*)d_in[1];   // (B,)   int32
    // d_in[2] (x_steps) is the compile-time constant X_DIM = 1024.

    float* weights_out = (float*)d_out;                         // B*Y floats
    float* hist_out    = (float*)d_out + (size_t)B_DIM * Y_DIM; // B*X floats

    duration_calc_kernel<<<2 * B_DIM, 512>>>(duration, output_length,
                                             weights_out, hist_out);
}